// round 1
// baseline (speedup 1.0000x reference)
#include <cuda_runtime.h>

// Furthest Point Sampling: B=8 batches, N=65536 points, C=3, select 1024.
// 16 CTAs per batch cooperate via per-iteration atomicMax slot + counter barrier.

#define FPS_B  8
#define FPS_N  65536
#define FPS_NP 1024
#define FPS_K  16                      // CTAs per batch
#define FPS_T  512                     // threads per CTA
#define FPS_P  (FPS_N / (FPS_K * FPS_T))  // 8 points per thread
#define F4_PER (FPS_P / 4)             // 2 float4 loads per plane per thread

__device__ unsigned long long g_slots[FPS_B][FPS_NP];   // packed (dist_bits<<32)|(~idx)
__device__ unsigned int       g_counts[FPS_B][FPS_NP];  // barrier arrival counters
__device__ int                g_sel[FPS_B][FPS_NP];     // selected indices

__global__ void fps_init_kernel() {
    int i = blockIdx.x * blockDim.x + threadIdx.x;
    int total = FPS_B * FPS_NP;
    if (i < total) {
        ((unsigned long long*)g_slots)[i] = 0ull;
        ((unsigned int*)g_counts)[i] = 0u;
    }
    if (i < FPS_B) g_sel[i][0] = 0;   // FPS seeds with index 0
}

__global__ void __launch_bounds__(FPS_T, 1) fps_kernel(const float* __restrict__ pts) {
    const int cta = blockIdx.x;
    const int b   = cta >> 4;          // cta / FPS_K
    const int k   = cta & (FPS_K - 1); // cta % FPS_K
    const int tid = threadIdx.x;

    const float* __restrict__ xb = pts + (size_t)b * 3 * FPS_N;
    const float4* __restrict__ x4 = (const float4*)(xb);
    const float4* __restrict__ y4 = (const float4*)(xb + FPS_N);
    const float4* __restrict__ z4 = (const float4*)(xb + 2 * FPS_N);

    float x[FPS_P], y[FPS_P], z[FPS_P], dist[FPS_P];
    int fbase[F4_PER];

#pragma unroll
    for (int j = 0; j < F4_PER; j++) {
        int f = k * (FPS_N / 4 / FPS_K) + tid + FPS_T * j;
        fbase[j] = 4 * f;
        float4 vx = x4[f];
        float4 vy = y4[f];
        float4 vz = z4[f];
        x[4*j+0] = vx.x; x[4*j+1] = vx.y; x[4*j+2] = vx.z; x[4*j+3] = vx.w;
        y[4*j+0] = vy.x; y[4*j+1] = vy.y; y[4*j+2] = vy.z; y[4*j+3] = vy.w;
        z[4*j+0] = vz.x; z[4*j+1] = vz.y; z[4*j+2] = vz.z; z[4*j+3] = vz.w;
    }
#pragma unroll
    for (int p = 0; p < FPS_P; p++) dist[p] = 1e10f;

    __shared__ unsigned long long s_red[FPS_T / 32];
    __shared__ int s_idx;

    // first selected point is index 0
    float px = __ldg(&xb[0]);
    float py = __ldg(&xb[FPS_N]);
    float pz = __ldg(&xb[2 * FPS_N]);

    for (int it = 1; it < FPS_NP; it++) {
        float bestd  = -1.0f;
        int   bestid = 0;
#pragma unroll
        for (int j = 0; j < F4_PER; j++) {
#pragma unroll
            for (int e = 0; e < 4; e++) {
                const int p = 4 * j + e;
                // match XLA: separate rounding, sum order (dx^2 + dy^2) + dz^2, no FMA
                float dx = __fsub_rn(x[p], px);
                float dy = __fsub_rn(y[p], py);
                float dz = __fsub_rn(z[p], pz);
                float d  = __fadd_rn(__fadd_rn(__fmul_rn(dx, dx), __fmul_rn(dy, dy)),
                                     __fmul_rn(dz, dz));
                float nd = fminf(dist[p], d);
                dist[p]  = nd;
                if (nd > bestd) { bestd = nd; bestid = fbase[j] + e; }  // strict >: first idx wins
            }
        }
        // packed key: higher dist wins; tie -> smaller index wins (matches jnp.argmax)
        unsigned long long packed =
            ((unsigned long long)__float_as_uint(bestd) << 32) |
            (unsigned long long)(0xFFFFFFFFu - (unsigned)bestid);

        // warp reduce (max of packed)
#pragma unroll
        for (int off = 16; off; off >>= 1) {
            unsigned long long o = __shfl_xor_sync(0xFFFFFFFFu, packed, off);
            packed = (o > packed) ? o : packed;
        }
        const int wid = tid >> 5;
        if ((tid & 31) == 0) s_red[wid] = packed;
        __syncthreads();

        if (tid < 32) {
            unsigned long long v = (tid < (FPS_T / 32)) ? s_red[tid] : 0ull;
#pragma unroll
            for (int off = 8; off; off >>= 1) {
                unsigned long long o = __shfl_xor_sync(0xFFFFFFFFu, v, off);
                v = (o > v) ? o : v;
            }
            if (tid == 0) {
                atomicMax(&g_slots[b][it], v);
                __threadfence();
                atomicAdd(&g_counts[b][it], 1u);
                // spin until all FPS_K CTAs of this batch arrived
                volatile unsigned int* cp = &g_counts[b][it];
                while (*cp < FPS_K) { }
                __threadfence();
                unsigned long long w = *(volatile unsigned long long*)&g_slots[b][it];
                int widx = (int)(0xFFFFFFFFu - (unsigned)(w & 0xFFFFFFFFull));
                s_idx = widx;
                if (k == 0) g_sel[b][it] = widx;
            }
        }
        __syncthreads();
        const int widx = s_idx;
        // fetch winner coords (same address per warp -> broadcast, L2 hit)
        px = __ldcg(&xb[widx]);
        py = __ldcg(&xb[FPS_N + widx]);
        pz = __ldcg(&xb[2 * FPS_N + widx]);
    }
}

__global__ void fps_gather_kernel(const float* __restrict__ pts, float* __restrict__ out) {
    int i = blockIdx.x * blockDim.x + threadIdx.x;   // over B*3*NP = 24576
    if (i >= FPS_B * 3 * FPS_NP) return;
    int ip = i & (FPS_NP - 1);
    int c  = (i / FPS_NP) % 3;
    int b  = i / (3 * FPS_NP);
    int idx = g_sel[b][ip];
    out[i] = pts[((size_t)b * 3 + c) * FPS_N + idx];
}

extern "C" void kernel_launch(void* const* d_in, const int* in_sizes, int n_in,
                              void* d_out, int out_size) {
    const float* pts = (const float*)d_in[0];
    float* out = (float*)d_out;

    fps_init_kernel<<<(FPS_B * FPS_NP + 255) / 256, 256>>>();
    fps_kernel<<<FPS_B * FPS_K, FPS_T>>>(pts);
    fps_gather_kernel<<<(FPS_B * 3 * FPS_NP + 255) / 256, 256>>>(pts, out);
}

// round 2
// speedup vs baseline: 1.4158x; 1.4158x over previous
#include <cuda_runtime.h>
#include <cstdint>

// FPS: B=8, N=65536, C=3, select 1024.
// 8-CTA cluster per batch; DSMEM all-to-all candidate broadcast + barrier.cluster.
// Packed f32x2 math halves fma-pipe instruction count (bitwise-identical rounding).

#define FPS_B  8
#define FPS_N  65536
#define FPS_NP 1024
#define FPS_CL 8          // CTAs per batch = cluster size
#define FPS_T  1024       // threads per CTA
#define FPS_P  8          // points per thread  (8*1024*8 = 65536)

__device__ int g_sel[FPS_B][FPS_NP];

__device__ __forceinline__ uint64_t pack2(float a, float b) {
    uint64_t r; asm("mov.b64 %0, {%1, %2};" : "=l"(r) : "f"(a), "f"(b)); return r;
}
__device__ __forceinline__ void unpack2(uint64_t v, float& a, float& b) {
    asm("mov.b64 {%0, %1}, %2;" : "=f"(a), "=f"(b) : "l"(v));
}
__device__ __forceinline__ uint64_t add2(uint64_t a, uint64_t b) {
    uint64_t r; asm("add.rn.f32x2 %0, %1, %2;" : "=l"(r) : "l"(a), "l"(b)); return r;
}
__device__ __forceinline__ uint64_t mul2(uint64_t a, uint64_t b) {
    uint64_t r; asm("mul.rn.f32x2 %0, %1, %2;" : "=l"(r) : "l"(a), "l"(b)); return r;
}
__device__ __forceinline__ uint32_t ctarank() {
    uint32_t r; asm("mov.u32 %0, %%cluster_ctarank;" : "=r"(r)); return r;
}
__device__ __forceinline__ uint32_t smem_u32(const void* p) {
    uint32_t a;
    asm("{ .reg .u64 t; cvta.to.shared.u64 t, %1; cvt.u32.u64 %0, t; }" : "=r"(a) : "l"(p));
    return a;
}

__global__ void __launch_bounds__(FPS_T, 1) __cluster_dims__(FPS_CL, 1, 1)
fps_kernel(const float* __restrict__ pts) {
    const int b      = blockIdx.x / FPS_CL;
    const uint32_t k = ctarank();
    const int tid    = threadIdx.x;

    const float* __restrict__ xb = pts + (size_t)b * 3 * FPS_N;
    const float4* __restrict__ x4 = (const float4*)(xb);
    const float4* __restrict__ y4 = (const float4*)(xb + FPS_N);
    const float4* __restrict__ z4 = (const float4*)(xb + 2 * FPS_N);

    // 8 points per thread, packed as 4 f32x2 pairs per coordinate.
    uint64_t xp[4], yp[4], zp[4];
    float dist[FPS_P];
    int pbase[2];

#pragma unroll
    for (int j = 0; j < 2; j++) {
        int f = (int)k * (FPS_N / 4 / FPS_CL) + tid + FPS_T * j;  // float4 index in plane
        pbase[j] = 4 * f;
        float4 vx = x4[f], vy = y4[f], vz = z4[f];
        xp[2*j+0] = pack2(vx.x, vx.y);  xp[2*j+1] = pack2(vx.z, vx.w);
        yp[2*j+0] = pack2(vy.x, vy.y);  yp[2*j+1] = pack2(vy.z, vy.w);
        zp[2*j+0] = pack2(vz.x, vz.y);  zp[2*j+1] = pack2(vz.z, vz.w);
    }
#pragma unroll
    for (int p = 0; p < FPS_P; p++) dist[p] = 1e10f;

    __shared__ unsigned long long s_red[FPS_T / 32];   // 32 warp leaders
    __shared__ unsigned long long s_slots[FPS_CL];     // one candidate per cluster CTA

    if (k == 0 && tid == 0) g_sel[b][0] = 0;           // seed index

    // first pivot = point 0
    float px = __ldg(&xb[0]);
    float py = __ldg(&xb[FPS_N]);
    float pz = __ldg(&xb[2 * FPS_N]);

    const uint32_t slot_addr = smem_u32(&s_slots[k]);

    for (int it = 1; it < FPS_NP; it++) {
        // packed negated pivot: add(x, -px) is bitwise == sub(x, px)
        uint64_t npx = pack2(-px, -px);
        uint64_t npy = pack2(-py, -py);
        uint64_t npz = pack2(-pz, -pz);

        float bestd  = -1.0f;
        int   bestid = 0;
#pragma unroll
        for (int q = 0; q < 4; q++) {
            uint64_t dx = add2(xp[q], npx);
            uint64_t dy = add2(yp[q], npy);
            uint64_t dz = add2(zp[q], npz);
            // match XLA order: (dx^2 + dy^2) + dz^2, separate rn rounding
            uint64_t s = add2(add2(mul2(dx, dx), mul2(dy, dy)), mul2(dz, dz));
            float d0, d1; unpack2(s, d0, d1);
            const int p   = 2 * q;
            const int idx = pbase[q >> 1] + 2 * (q & 1);
            float n0 = fminf(dist[p], d0);     dist[p]     = n0;
            if (n0 > bestd) { bestd = n0; bestid = idx; }       // strict >: first idx wins
            float n1 = fminf(dist[p + 1], d1); dist[p + 1] = n1;
            if (n1 > bestd) { bestd = n1; bestid = idx + 1; }
        }

        // packed key: higher dist wins; tie -> smaller index (matches jnp.argmax)
        unsigned long long key =
            ((unsigned long long)__float_as_uint(bestd) << 32) |
            (unsigned long long)(0xFFFFFFFFu - (unsigned)bestid);

#pragma unroll
        for (int off = 16; off; off >>= 1) {
            unsigned long long o = __shfl_xor_sync(0xFFFFFFFFu, key, off);
            key = (o > key) ? o : key;
        }
        if ((tid & 31) == 0) s_red[tid >> 5] = key;
        __syncthreads();

        if (tid < 32) {
            unsigned long long v = s_red[tid];   // 32 warps -> every lane valid
#pragma unroll
            for (int off = 16; off; off >>= 1) {
                unsigned long long o = __shfl_xor_sync(0xFFFFFFFFu, v, off);
                v = (o > v) ? o : v;
            }
            if (tid == 0) {
                // broadcast CTA candidate into every cluster CTA's s_slots[k]
#pragma unroll
                for (int r = 0; r < FPS_CL; r++) {
                    uint32_t raddr;
                    asm("mapa.shared::cluster.u32 %0, %1, %2;"
                        : "=r"(raddr) : "r"(slot_addr), "r"(r));
                    asm volatile("st.shared::cluster.u64 [%0], %1;"
                                 :: "r"(raddr), "l"(v) : "memory");
                }
            }
        }
        // release/acquire cluster barrier: orders the DSMEM stores, syncs CTA too
        asm volatile("barrier.cluster.arrive.aligned;" ::: "memory");
        asm volatile("barrier.cluster.wait.aligned;"   ::: "memory");

        // every thread reduces the 8 slots locally (no further sync needed)
        unsigned long long w = s_slots[0];
#pragma unroll
        for (int r = 1; r < FPS_CL; r++) {
            unsigned long long o = s_slots[r];
            w = (o > w) ? o : w;
        }
        const int widx = (int)(0xFFFFFFFFu - (unsigned)(w & 0xFFFFFFFFull));

        if (k == 0 && tid == 0) g_sel[b][it] = widx;   // off critical path

        px = __ldcg(&xb[widx]);
        py = __ldcg(&xb[FPS_N + widx]);
        pz = __ldcg(&xb[2 * FPS_N + widx]);
    }
}

__global__ void fps_gather_kernel(const float* __restrict__ pts, float* __restrict__ out) {
    int i = blockIdx.x * blockDim.x + threadIdx.x;   // B*3*NP = 24576
    if (i >= FPS_B * 3 * FPS_NP) return;
    int ip = i & (FPS_NP - 1);
    int c  = (i / FPS_NP) % 3;
    int b  = i / (3 * FPS_NP);
    int idx = g_sel[b][ip];
    out[i] = pts[((size_t)b * 3 + c) * FPS_N + idx];
}

extern "C" void kernel_launch(void* const* d_in, const int* in_sizes, int n_in,
                              void* d_out, int out_size) {
    const float* pts = (const float*)d_in[0];
    float* out = (float*)d_out;

    fps_kernel<<<FPS_B * FPS_CL, FPS_T>>>(pts);
    fps_gather_kernel<<<(FPS_B * 3 * FPS_NP + 255) / 256, 256>>>(pts, out);
}

// round 3
// speedup vs baseline: 1.7853x; 1.2611x over previous
#include <cuda_runtime.h>
#include <cstdint>

// FPS: B=8, N=65536, select 1024.
// 8-CTA cluster per batch. Per-iteration candidate exchange via st.async +
// mbarrier (double-buffered), redux.sync warp argmax, in-kernel final gather.

#define FPS_B  8
#define FPS_N  65536
#define FPS_NP 1024
#define FPS_CL 8          // CTAs per batch = cluster size
#define FPS_T  1024       // threads per CTA
#define FPS_P  8          // points per thread
#define NW     (FPS_T/32) // 32 warps

__device__ __forceinline__ uint64_t pack2(float a, float b) {
    uint64_t r; asm("mov.b64 %0, {%1, %2};" : "=l"(r) : "f"(a), "f"(b)); return r;
}
__device__ __forceinline__ void unpack2(uint64_t v, float& a, float& b) {
    asm("mov.b64 {%0, %1}, %2;" : "=f"(a), "=f"(b) : "l"(v));
}
__device__ __forceinline__ uint64_t add2(uint64_t a, uint64_t b) {
    uint64_t r; asm("add.rn.f32x2 %0, %1, %2;" : "=l"(r) : "l"(a), "l"(b)); return r;
}
__device__ __forceinline__ uint64_t mul2(uint64_t a, uint64_t b) {
    uint64_t r; asm("mul.rn.f32x2 %0, %1, %2;" : "=l"(r) : "l"(a), "l"(b)); return r;
}
__device__ __forceinline__ uint32_t ctarank() {
    uint32_t r; asm("mov.u32 %0, %%cluster_ctarank;" : "=r"(r)); return r;
}
__device__ __forceinline__ uint32_t smem_u32(const void* p) {
    uint32_t a;
    asm("{ .reg .u64 t; cvta.to.shared.u64 t, %1; cvt.u32.u64 %0, t; }" : "=r"(a) : "l"(p));
    return a;
}
__device__ __forceinline__ uint32_t redux_max_u32(uint32_t v) {
    uint32_t r; asm("redux.sync.max.u32 %0, %1, 0xFFFFFFFF;" : "=r"(r) : "r"(v)); return r;
}
__device__ __forceinline__ uint32_t redux_min_u32(uint32_t v) {
    uint32_t r; asm("redux.sync.min.u32 %0, %1, 0xFFFFFFFF;" : "=r"(r) : "r"(v)); return r;
}
__device__ __forceinline__ void mbar_init(uint32_t mbar, uint32_t cnt) {
    asm volatile("mbarrier.init.shared.b64 [%0], %1;" :: "r"(mbar), "r"(cnt) : "memory");
}
__device__ __forceinline__ void mbar_expect_tx(uint32_t mbar, uint32_t bytes) {
    asm volatile("mbarrier.arrive.expect_tx.shared.b64 _, [%0], %1;"
                 :: "r"(mbar), "r"(bytes) : "memory");
}
__device__ __forceinline__ void mbar_wait(uint32_t mbar, uint32_t parity) {
    asm volatile(
        "{\n\t"
        ".reg .pred P;\n\t"
        "WL_%=:\n\t"
        "mbarrier.try_wait.parity.acquire.cluster.shared::cta.b64 P, [%0], %1, 0x989680;\n\t"
        "@P bra.uni WD_%=;\n\t"
        "bra.uni WL_%=;\n\t"
        "WD_%=:\n\t"
        "}"
        :: "r"(mbar), "r"(parity) : "memory");
}
__device__ __forceinline__ uint32_t mapa32(uint32_t laddr, uint32_t rank) {
    uint32_t r;
    asm("mapa.shared::cluster.u32 %0, %1, %2;" : "=r"(r) : "r"(laddr), "r"(rank));
    return r;
}
__device__ __forceinline__ void st_async_u64(uint32_t raddr, uint64_t v, uint32_t rmbar) {
    asm volatile("st.async.shared::cluster.mbarrier::complete_tx::bytes.b64 [%0], %1, [%2];"
                 :: "r"(raddr), "l"(v), "r"(rmbar) : "memory");
}

__global__ void __launch_bounds__(FPS_T, 1) __cluster_dims__(FPS_CL, 1, 1)
fps_kernel(const float* __restrict__ pts, float* __restrict__ out) {
    const int b      = blockIdx.x / FPS_CL;
    const uint32_t k = ctarank();
    const int tid    = threadIdx.x;

    const float* __restrict__ xb = pts + (size_t)b * 3 * FPS_N;
    const float4* __restrict__ x4 = (const float4*)(xb);
    const float4* __restrict__ y4 = (const float4*)(xb + FPS_N);
    const float4* __restrict__ z4 = (const float4*)(xb + 2 * FPS_N);

    uint64_t xp[4], yp[4], zp[4];
    float dist[FPS_P];
    int pbase[2];

#pragma unroll
    for (int j = 0; j < 2; j++) {
        int f = (int)k * (FPS_N / 4 / FPS_CL) + tid + FPS_T * j;
        pbase[j] = 4 * f;
        float4 vx = x4[f], vy = y4[f], vz = z4[f];
        xp[2*j+0] = pack2(vx.x, vx.y);  xp[2*j+1] = pack2(vx.z, vx.w);
        yp[2*j+0] = pack2(vy.x, vy.y);  yp[2*j+1] = pack2(vy.z, vy.w);
        zp[2*j+0] = pack2(vz.x, vz.y);  zp[2*j+1] = pack2(vz.z, vz.w);
    }
#pragma unroll
    for (int p = 0; p < FPS_P; p++) dist[p] = 1e10f;

    __shared__ uint32_t s_wd[NW], s_wi[NW];
    __shared__ alignas(16) unsigned long long s_key[2][FPS_CL];  // exchange slots
    __shared__ alignas(8)  unsigned long long s_mbar[2];
    __shared__ uint32_t s_hist[FPS_NP];

    const uint32_t mb0 = smem_u32(&s_mbar[0]);
    const uint32_t mb1 = smem_u32(&s_mbar[1]);
    const uint32_t slot0 = smem_u32(&s_key[0][k]);   // my slot in buffer 0
    const uint32_t slot1 = smem_u32(&s_key[1][k]);

    if (tid == 0) {
        mbar_init(mb0, 1);
        mbar_init(mb1, 1);
        s_hist[0] = 0;
    }
    __syncthreads();
    // all mbarriers across the cluster must be live before any st.async
    asm volatile("barrier.cluster.arrive.aligned;" ::: "memory");
    asm volatile("barrier.cluster.wait.aligned;"   ::: "memory");

    // first pivot = point 0
    float px = __ldg(&xb[0]);
    float py = __ldg(&xb[FPS_N]);
    float pz = __ldg(&xb[2 * FPS_N]);

    for (int it = 1; it < FPS_NP; it++) {
        const int u      = it - 1;
        const int buf    = u & 1;
        const uint32_t par = (u >> 1) & 1;
        const uint32_t mb   = buf ? mb1 : mb0;
        const uint32_t slot = buf ? slot1 : slot0;

        uint64_t npx = pack2(-px, -px);
        uint64_t npy = pack2(-py, -py);
        uint64_t npz = pack2(-pz, -pz);

        float bestd  = -1.0f;
        int   bestid = 0;
#pragma unroll
        for (int q = 0; q < 4; q++) {
            uint64_t dx = add2(xp[q], npx);   // add(x,-p) bitwise == sub(x,p)
            uint64_t dy = add2(yp[q], npy);
            uint64_t dz = add2(zp[q], npz);
            uint64_t s = add2(add2(mul2(dx, dx), mul2(dy, dy)), mul2(dz, dz));
            float d0, d1; unpack2(s, d0, d1);
            const int p   = 2 * q;
            const int idx = pbase[q >> 1] + 2 * (q & 1);
            float n0 = fminf(dist[p], d0);     dist[p]     = n0;
            if (n0 > bestd) { bestd = n0; bestid = idx; }
            float n1 = fminf(dist[p + 1], d1); dist[p + 1] = n1;
            if (n1 > bestd) { bestd = n1; bestid = idx + 1; }
        }

        // warp argmax via redux (dists >= 0 so u32 order == float order)
        uint32_t db   = __float_as_uint(bestd);
        uint32_t wmax = redux_max_u32(db);
        uint32_t cand = (db == wmax) ? (uint32_t)bestid : 0xFFFFFFFFu;
        uint32_t wmin = redux_min_u32(cand);       // smallest idx among tied
        if (db == wmax && (uint32_t)bestid == wmin) {   // unique owner lane
            s_wd[tid >> 5] = wmax;
            s_wi[tid >> 5] = wmin;
        }
        __syncthreads();

        if (tid < 32) {   // NW == 32: warp0 reduces the 32 warp winners
            uint32_t d = s_wd[tid], i = s_wi[tid];
            uint32_t m  = redux_max_u32(d);
            uint32_t c2 = (d == m) ? i : 0xFFFFFFFFu;
            uint32_t mi = redux_min_u32(c2);
            if (d == m && i == mi) {          // unique owner lane of CTA winner
                uint64_t key = ((uint64_t)m << 32) |
                               (uint64_t)(0xFFFFFFFFu - mi);
                mbar_expect_tx(mb, 8 * FPS_CL);        // expect 64 bytes
#pragma unroll
                for (int r = 0; r < FPS_CL; r++) {
                    uint32_t rs = mapa32(slot, (uint32_t)r);
                    uint32_t rm = mapa32(mb,   (uint32_t)r);
                    st_async_u64(rs, key, rm);
                }
            }
        }

        mbar_wait(mb, par);

        // reduce the 8 exchanged keys (identical in every CTA)
        const ulonglong2* kp = (const ulonglong2*)&s_key[buf][0];
        ulonglong2 a0 = kp[0], a1 = kp[1], a2 = kp[2], a3 = kp[3];
        unsigned long long m0 = (a0.x > a0.y) ? a0.x : a0.y;
        unsigned long long m1 = (a1.x > a1.y) ? a1.x : a1.y;
        unsigned long long m2 = (a2.x > a2.y) ? a2.x : a2.y;
        unsigned long long m3 = (a3.x > a3.y) ? a3.x : a3.y;
        unsigned long long n0 = (m0 > m1) ? m0 : m1;
        unsigned long long n1 = (m2 > m3) ? m2 : m3;
        unsigned long long w  = (n0 > n1) ? n0 : n1;
        const int widx = (int)(0xFFFFFFFFu - (unsigned)(w & 0xFFFFFFFFull));

        if (tid == 0) s_hist[it] = (uint32_t)widx;

        px = __ldcg(&xb[widx]);
        py = __ldcg(&xb[FPS_N + widx]);
        pz = __ldcg(&xb[2 * FPS_N + widx]);
    }

    // final gather: rank-0 CTA of each cluster writes (3, 1024) for its batch
    __syncthreads();
    if (k == 0) {
#pragma unroll
        for (int i = tid; i < 3 * FPS_NP; i += FPS_T) {
            int ip = i & (FPS_NP - 1);
            int c  = i >> 10;
            uint32_t idx = s_hist[ip];
            out[((size_t)b * 3 + c) * FPS_NP + i - (c << 10) + 0] =
                xb[(size_t)c * FPS_N + idx];
        }
    }
}

extern "C" void kernel_launch(void* const* d_in, const int* in_sizes, int n_in,
                              void* d_out, int out_size) {
    const float* pts = (const float*)d_in[0];
    float* out = (float*)d_out;
    fps_kernel<<<FPS_B * FPS_CL, FPS_T>>>(pts, out);
}

// round 4
// speedup vs baseline: 2.2755x; 1.2746x over previous
#include <cuda_runtime.h>
#include <cstdint>

// FPS: B=8, N=65536, select 1024.
// One cluster per batch (16 CTAs preferred, 8 fallback). st.async + mbarrier
// candidate exchange, redux.sync argmax, bar.arrive/sync split, in-kernel gather.

#define FPS_B  8
#define FPS_N  65536
#define FPS_NP 1024
#define FPS_T  1024
#define NW     (FPS_T / 32)

__device__ __forceinline__ uint64_t pack2(float a, float b) {
    uint64_t r; asm("mov.b64 %0, {%1, %2};" : "=l"(r) : "f"(a), "f"(b)); return r;
}
__device__ __forceinline__ void unpack2(uint64_t v, float& a, float& b) {
    asm("mov.b64 {%0, %1}, %2;" : "=f"(a), "=f"(b) : "l"(v));
}
__device__ __forceinline__ uint64_t add2(uint64_t a, uint64_t b) {
    uint64_t r; asm("add.rn.f32x2 %0, %1, %2;" : "=l"(r) : "l"(a), "l"(b)); return r;
}
__device__ __forceinline__ uint64_t mul2(uint64_t a, uint64_t b) {
    uint64_t r; asm("mul.rn.f32x2 %0, %1, %2;" : "=l"(r) : "l"(a), "l"(b)); return r;
}
__device__ __forceinline__ uint32_t ctarank() {
    uint32_t r; asm("mov.u32 %0, %%cluster_ctarank;" : "=r"(r)); return r;
}
__device__ __forceinline__ uint32_t smem_u32(const void* p) {
    uint32_t a;
    asm("{ .reg .u64 t; cvta.to.shared.u64 t, %1; cvt.u32.u64 %0, t; }" : "=r"(a) : "l"(p));
    return a;
}
__device__ __forceinline__ uint32_t redux_max_u32(uint32_t v) {
    uint32_t r; asm("redux.sync.max.u32 %0, %1, 0xFFFFFFFF;" : "=r"(r) : "r"(v)); return r;
}
__device__ __forceinline__ uint32_t redux_min_u32(uint32_t v) {
    uint32_t r; asm("redux.sync.min.u32 %0, %1, 0xFFFFFFFF;" : "=r"(r) : "r"(v)); return r;
}
__device__ __forceinline__ void mbar_init(uint32_t mbar, uint32_t cnt) {
    asm volatile("mbarrier.init.shared.b64 [%0], %1;" :: "r"(mbar), "r"(cnt) : "memory");
}
__device__ __forceinline__ void mbar_expect_tx(uint32_t mbar, uint32_t bytes) {
    asm volatile("mbarrier.arrive.expect_tx.shared.b64 _, [%0], %1;"
                 :: "r"(mbar), "r"(bytes) : "memory");
}
__device__ __forceinline__ void mbar_wait(uint32_t mbar, uint32_t parity) {
    asm volatile(
        "{\n\t"
        ".reg .pred P;\n\t"
        "WL_%=:\n\t"
        "mbarrier.try_wait.parity.acquire.cluster.shared::cta.b64 P, [%0], %1, 0x989680;\n\t"
        "@P bra.uni WD_%=;\n\t"
        "bra.uni WL_%=;\n\t"
        "WD_%=:\n\t"
        "}"
        :: "r"(mbar), "r"(parity) : "memory");
}
__device__ __forceinline__ uint32_t mapa32(uint32_t laddr, uint32_t rank) {
    uint32_t r;
    asm("mapa.shared::cluster.u32 %0, %1, %2;" : "=r"(r) : "r"(laddr), "r"(rank));
    return r;
}
__device__ __forceinline__ void st_async_u64(uint32_t raddr, uint64_t v, uint32_t rmbar) {
    asm volatile("st.async.shared::cluster.mbarrier::complete_tx::bytes.b64 [%0], %1, [%2];"
                 :: "r"(raddr), "l"(v), "r"(rmbar) : "memory");
}
__device__ __forceinline__ void lds_v2(uint32_t addr, uint32_t& a, uint32_t& b) {
    asm volatile("ld.shared.v2.u32 {%0, %1}, [%2];" : "=r"(a), "=r"(b) : "r"(addr));
}

template<int CL>
__global__ void __launch_bounds__(FPS_T, 1)
fps_kernel(const float* __restrict__ pts, float* __restrict__ out) {
    constexpr int PT    = FPS_N / (CL * FPS_T);  // points per thread (4 or 8)
    constexpr int NF4   = PT / 4;                // float4 loads per plane
    constexpr int NPAIR = PT / 2;                // f32x2 pairs
    constexpr uint32_t XBYTES = 8u * CL;         // exchange bytes per phase

    const int b      = blockIdx.x / CL;
    const uint32_t k = ctarank();
    const int tid    = threadIdx.x;
    const int lane   = tid & 31;
    const int wid    = tid >> 5;

    const float* __restrict__ xb = pts + (size_t)b * 3 * FPS_N;
    const float4* __restrict__ x4 = (const float4*)(xb);
    const float4* __restrict__ y4 = (const float4*)(xb + FPS_N);
    const float4* __restrict__ z4 = (const float4*)(xb + 2 * FPS_N);

    uint64_t xp[NPAIR], yp[NPAIR], zp[NPAIR];
    float dist[PT];
    int pbase[NF4];

#pragma unroll
    for (int j = 0; j < NF4; j++) {
        int f = (int)k * (FPS_N / 4 / CL) + tid + FPS_T * j;
        pbase[j] = 4 * f;
        float4 vx = x4[f], vy = y4[f], vz = z4[f];
        xp[2*j+0] = pack2(vx.x, vx.y);  xp[2*j+1] = pack2(vx.z, vx.w);
        yp[2*j+0] = pack2(vy.x, vy.y);  yp[2*j+1] = pack2(vy.z, vy.w);
        zp[2*j+0] = pack2(vz.x, vz.y);  zp[2*j+1] = pack2(vz.z, vz.w);
    }
#pragma unroll
    for (int p = 0; p < PT; p++) dist[p] = 1e10f;

    __shared__ uint32_t s_wd[NW], s_wi[NW];
    __shared__ alignas(16) uint64_t s_pair[2][CL];   // exchange: lo=d, hi=~idx
    __shared__ alignas(8)  uint64_t s_mbar[2];
    __shared__ uint32_t s_hist[FPS_NP];

    const uint32_t mb0 = smem_u32(&s_mbar[0]);
    const uint32_t mb1 = smem_u32(&s_mbar[1]);
    const uint32_t pair0 = smem_u32(&s_pair[0][0]);
    const uint32_t pair1 = smem_u32(&s_pair[1][0]);

    // per-lane precomputed remote addresses for the all-to-all send (warp0, lane<CL)
    uint32_t r_slot0 = 0, r_slot1 = 0, r_mb0 = 0, r_mb1 = 0;
    if (wid == 0 && lane < CL) {
        r_slot0 = mapa32(pair0 + 8u * k, (uint32_t)lane);
        r_slot1 = mapa32(pair1 + 8u * k, (uint32_t)lane);
        r_mb0   = mapa32(mb0, (uint32_t)lane);
        r_mb1   = mapa32(mb1, (uint32_t)lane);
    }

    if (tid == 0) {
        mbar_init(mb0, 1);
        mbar_init(mb1, 1);
        mbar_expect_tx(mb0, XBYTES);   // phase 0 of each buffer
        mbar_expect_tx(mb1, XBYTES);
        s_hist[0] = 0;
    }
    __syncthreads();
    asm volatile("barrier.cluster.arrive.aligned;" ::: "memory");
    asm volatile("barrier.cluster.wait.aligned;"   ::: "memory");

    float px = __ldg(&xb[0]);
    float py = __ldg(&xb[FPS_N]);
    float pz = __ldg(&xb[2 * FPS_N]);

    for (int it = 1; it < FPS_NP; it++) {
        const int u        = it - 1;
        const int buf      = u & 1;
        const uint32_t par = (u >> 1) & 1;
        const uint32_t mb     = buf ? mb1 : mb0;
        const uint32_t pbuf   = buf ? pair1 : pair0;
        const uint32_t r_slot = buf ? r_slot1 : r_slot0;
        const uint32_t r_mb   = buf ? r_mb1 : r_mb0;

        uint64_t npx = pack2(-px, -px);
        uint64_t npy = pack2(-py, -py);
        uint64_t npz = pack2(-pz, -pz);

        float bestd  = -1.0f;
        int   bestid = 0;
#pragma unroll
        for (int q = 0; q < NPAIR; q++) {
            uint64_t dx = add2(xp[q], npx);   // add(x,-p) bitwise == sub(x,p)
            uint64_t dy = add2(yp[q], npy);
            uint64_t dz = add2(zp[q], npz);
            // XLA order: (dx^2 + dy^2) + dz^2, separate .rn rounding
            uint64_t s = add2(add2(mul2(dx, dx), mul2(dy, dy)), mul2(dz, dz));
            float d0, d1; unpack2(s, d0, d1);
            const int p   = 2 * q;
            const int idx = pbase[q >> 1] + 2 * (q & 1);
            float n0 = fminf(dist[p], d0);     dist[p]     = n0;
            if (n0 > bestd) { bestd = n0; bestid = idx; }      // strict >: first idx wins
            float n1 = fminf(dist[p + 1], d1); dist[p + 1] = n1;
            if (n1 > bestd) { bestd = n1; bestid = idx + 1; }
        }

        // warp argmax (dists >= 0: u32 order == float order); first-index tie-break
        uint32_t db   = __float_as_uint(bestd);
        uint32_t wmax = redux_max_u32(db);
        uint32_t cand = (db == wmax) ? (uint32_t)bestid : 0xFFFFFFFFu;
        uint32_t wmin = redux_min_u32(cand);
        if (lane == 0) { s_wd[wid] = wmax; s_wi[wid] = wmin; }

        if (wid == 0) {
            asm volatile("bar.sync 1, %0;" :: "r"(FPS_T) : "memory");
            uint32_t d = s_wd[lane], i = s_wi[lane];     // NW == 32
            uint32_t m  = redux_max_u32(d);
            uint32_t c2 = (d == m) ? i : 0xFFFFFFFFu;
            uint32_t mi = redux_min_u32(c2);
            if (lane < CL) {
                uint64_t msg = ((uint64_t)(~mi) << 32) | (uint64_t)m;  // lo=d, hi=~i
                st_async_u64(r_slot, msg, r_mb);
            }
        } else {
            asm volatile("bar.arrive 1, %0;" :: "r"(FPS_T) : "memory");
        }

        mbar_wait(mb, par);

        // per-warp slot reduce: 1 LDS.v2 + 2 redux
        uint32_t d = 0, ni = 0;
        if (lane < CL) lds_v2(pbuf + 8u * (uint32_t)lane, d, ni);
        uint32_t dm = redux_max_u32(d);
        uint32_t c3 = (lane < CL && d == dm) ? ni : 0u;
        uint32_t nim = redux_max_u32(c3);          // largest ~i == smallest i
        const int widx = (int)(~nim);

        if (tid == 0) {
            s_hist[it] = (uint32_t)widx;
            mbar_expect_tx(mb, XBYTES);            // next phase of this buffer
        }

        px = __ldcg(&xb[widx]);
        py = __ldcg(&xb[FPS_N + widx]);
        pz = __ldcg(&xb[2 * FPS_N + widx]);
    }

    // final gather: rank-0 CTA writes (3, 1024) for its batch
    __syncthreads();
    if (k == 0) {
        for (int i = tid; i < 3 * FPS_NP; i += FPS_T) {
            int ip = i & (FPS_NP - 1);
            int c  = i >> 10;
            uint32_t idx = s_hist[ip];
            out[((size_t)b * 3 + c) * FPS_NP + ip] = xb[(size_t)c * FPS_N + idx];
        }
    }
}

extern "C" void kernel_launch(void* const* d_in, const int* in_sizes, int n_in,
                              void* d_out, int out_size) {
    const float* pts = (const float*)d_in[0];
    float* out = (float*)d_out;

    cudaLaunchConfig_t cfg = {};
    cfg.blockDim = dim3(FPS_T, 1, 1);
    cfg.stream = 0;
    cudaLaunchAttribute at[1];
    at[0].id = cudaLaunchAttributeClusterDimension;
    cfg.attrs = at;
    cfg.numAttrs = 1;

    // probe 16-CTA non-portable clusters (host-side query; capture-safe)
    bool ok16 = false;
    if (cudaFuncSetAttribute(fps_kernel<16>,
                             cudaFuncAttributeNonPortableClusterSizeAllowed, 1) == cudaSuccess) {
        cfg.gridDim = dim3(FPS_B * 16, 1, 1);
        at[0].val.clusterDim = {16, 1, 1};
        int nc = 0;
        if (cudaOccupancyMaxActiveClusters(&nc, fps_kernel<16>, &cfg) == cudaSuccess &&
            nc >= FPS_B)
            ok16 = true;
    }
    (void)cudaGetLastError();   // clear any probe error

    if (ok16) {
        cfg.gridDim = dim3(FPS_B * 16, 1, 1);
        at[0].val.clusterDim = {16, 1, 1};
        cudaLaunchKernelEx(&cfg, fps_kernel<16>, pts, out);
    } else {
        cfg.gridDim = dim3(FPS_B * 8, 1, 1);
        at[0].val.clusterDim = {8, 1, 1};
        cudaLaunchKernelEx(&cfg, fps_kernel<8>, pts, out);
    }
}